// round 8
// baseline (speedup 1.0000x reference)
#include <cuda_runtime.h>
#include <cuda_fp16.h>
#include <cstdint>

// ===================== problem constants =====================
constexpr int NTOK = 16384;     // 8*2048
constexpr int DDIM = 768;
constexpr int FDIM = 3072;
constexpr int NEXP = 8;
constexpr int CAP  = 2560;      // int(1.25*16384/8)

// ===================== device scratch (static; allocation-free) ==============
__device__ __half g_Xbuf[(size_t)NEXP * CAP * DDIM];   // [E][CAP][D] fp16
__device__ __half g_H   [(size_t)NEXP * CAP * FDIM];   // [E][CAP][F] fp16
__device__ __half g_w1t [(size_t)NEXP * FDIM * DDIM];  // [E][F][D] K-major fp16
__device__ __half g_w2t [(size_t)NEXP * DDIM * FDIM];  // [E][D][F] K-major fp16
__device__ int    g_route[NTOK];
__device__ float  g_prob [NTOK];
__device__ int    g_slot [NTOK];
__device__ int    g_tok  [NEXP * CAP];
__device__ int    g_cnt  [16];

// ===================== PTX helpers (sm_80-era, compute_103-safe) =============
__device__ __forceinline__ uint32_t smem_u32(const void* p) {
    uint32_t a;
    asm("{ .reg .u64 t; cvta.to.shared.u64 t, %1; cvt.u32.u64 %0, t; }"
        : "=r"(a) : "l"(p));
    return a;
}

#define CP_ASYNC16(dst_smem, src_gmem) \
    asm volatile("cp.async.cg.shared.global [%0], [%1], 16;" \
        :: "r"(dst_smem), "l"(src_gmem))
#define CP_COMMIT() asm volatile("cp.async.commit_group;" ::: "memory")
#define CP_WAIT(n)  asm volatile("cp.async.wait_group %0;" :: "n"(n) : "memory")

__device__ __forceinline__ void ldsm_x4(uint32_t& r0, uint32_t& r1,
                                        uint32_t& r2, uint32_t& r3, uint32_t addr) {
    asm volatile("ldmatrix.sync.aligned.m8n8.x4.shared.b16 {%0,%1,%2,%3}, [%4];"
        : "=r"(r0), "=r"(r1), "=r"(r2), "=r"(r3) : "r"(addr));
}

__device__ __forceinline__ void mma16816(float* d, const uint32_t* a, const uint32_t* b) {
    asm volatile(
        "mma.sync.aligned.m16n8k16.row.col.f32.f16.f16.f32 "
        "{%0,%1,%2,%3}, {%4,%5,%6,%7}, {%8,%9}, {%0,%1,%2,%3};"
        : "+f"(d[0]), "+f"(d[1]), "+f"(d[2]), "+f"(d[3])
        : "r"(a[0]), "r"(a[1]), "r"(a[2]), "r"(a[3]), "r"(b[0]), "r"(b[1]));
}

#define SMEM_SWIZZLE_128B(off) ((off) ^ (((off) >> 3) & 0x70))

// ===================== prep kernel: transposes + router fused ================
__global__ void zero_cnt_kernel() {
    if (threadIdx.x < 16) g_cnt[threadIdx.x] = 0;
}

constexpr int PREP_W1 = (FDIM / 32) * (DDIM / 32) * NEXP;   // 18432
constexpr int PREP_W2 = (DDIM / 32) * (FDIM / 32) * NEXP;   // 18432
constexpr int PREP_RT = NTOK / 16;                          // 1024
constexpr int PREP_BLOCKS = PREP_W1 + PREP_W2 + PREP_RT;

__device__ __forceinline__ void transpose_block(const float* __restrict__ in,
                                                __half* __restrict__ outp,
                                                int R, int C, int e, int cx, int ry,
                                                float tile[32][33]) {
    int c0 = cx * 32, r0 = ry * 32;
    const float* inp = in + (size_t)e * R * C;
    __half* op = outp + (size_t)e * R * C;
    int tx = threadIdx.x & 31, ty = threadIdx.x >> 5;
#pragma unroll
    for (int k = 0; k < 32; k += 8)
        tile[ty + k][tx] = inp[(size_t)(r0 + ty + k) * C + c0 + tx];
    __syncthreads();
#pragma unroll
    for (int k = 0; k < 32; k += 8)
        op[(size_t)(c0 + ty + k) * R + r0 + tx] = __float2half(tile[tx][ty + k]);
}

__device__ __forceinline__ void router_block(const float* __restrict__ x,
                                             const float* __restrict__ sw,
                                             const float* __restrict__ sb,
                                             int rb) {
    int w = rb * 8 + ((int)threadIdx.x >> 5);
    int lane = threadIdx.x & 31;
    int t0 = w * 2;
    const float* x0 = x + (size_t)t0 * DDIM;
    const float* x1 = x0 + DDIM;
    float a0[8], a1[8];
#pragma unroll
    for (int e = 0; e < 8; e++) { a0[e] = 0.f; a1[e] = 0.f; }
    for (int d = lane; d < DDIM; d += 32) {
        float xv0 = x0[d], xv1 = x1[d];
        const float4* wr = (const float4*)(sw + (size_t)d * 8);
        float4 w0 = wr[0], w1 = wr[1];
        a0[0] += xv0 * w0.x; a0[1] += xv0 * w0.y;
        a0[2] += xv0 * w0.z; a0[3] += xv0 * w0.w;
        a0[4] += xv0 * w1.x; a0[5] += xv0 * w1.y;
        a0[6] += xv0 * w1.z; a0[7] += xv0 * w1.w;
        a1[0] += xv1 * w0.x; a1[1] += xv1 * w0.y;
        a1[2] += xv1 * w0.z; a1[3] += xv1 * w0.w;
        a1[4] += xv1 * w1.x; a1[5] += xv1 * w1.y;
        a1[6] += xv1 * w1.z; a1[7] += xv1 * w1.w;
    }
#pragma unroll
    for (int off = 16; off; off >>= 1) {
#pragma unroll
        for (int e = 0; e < 8; e++) {
            a0[e] += __shfl_xor_sync(0xFFFFFFFFu, a0[e], off);
            a1[e] += __shfl_xor_sync(0xFFFFFFFFu, a1[e], off);
        }
    }
    if (lane == 0) {
#pragma unroll
        for (int pair = 0; pair < 2; ++pair) {
            float* acc = pair ? a1 : a0;
            int t = t0 + pair;
            float l[8];
            float best = -1e30f; int be = 0;
#pragma unroll
            for (int e = 0; e < 8; e++) {
                l[e] = acc[e] + sb[e];
                if (l[e] > best) { best = l[e]; be = e; }
            }
            float s = 0.f;
#pragma unroll
            for (int e = 0; e < 8; e++) s += expf(l[e] - best);
            float p = 1.0f / s;
            g_route[t] = be;
            g_prob[t] = p;
            int slot = atomicAdd(&g_cnt[be], 1);
            g_slot[t] = slot;
            if (slot < CAP) g_tok[be * CAP + slot] = t;
        }
    }
}

__global__ void __launch_bounds__(256) prep_kernel(const float* __restrict__ x,
                                                   const float* __restrict__ sw,
                                                   const float* __restrict__ sb,
                                                   const float* __restrict__ w1,
                                                   const float* __restrict__ w2) {
    __shared__ float tile[32][33];
    int b = blockIdx.x;
    if (b < PREP_W1) {
        int e = b / ((FDIM / 32) * (DDIM / 32));
        int rem = b % ((FDIM / 32) * (DDIM / 32));
        int cx = rem % (FDIM / 32), ry = rem / (FDIM / 32);
        transpose_block(w1, g_w1t, DDIM, FDIM, e, cx, ry, tile);
    } else if (b < PREP_W1 + PREP_W2) {
        int bb = b - PREP_W1;
        int e = bb / ((DDIM / 32) * (FDIM / 32));
        int rem = bb % ((DDIM / 32) * (FDIM / 32));
        int cx = rem % (DDIM / 32), ry = rem / (DDIM / 32);
        transpose_block(w2, g_w2t, FDIM, DDIM, e, cx, ry, tile);
    } else {
        router_block(x, sw, sb, b - PREP_W1 - PREP_W2);
    }
}

// gather + passthrough fused
__global__ void gather_kernel(const float* __restrict__ x, float* __restrict__ out) {
    int t = blockIdx.x;
    int e = g_route[t];
    int s = g_slot[t];
    const float4* src = (const float4*)(x + (size_t)t * DDIM);
    if (s < CAP) {
        __half2* dst = (__half2*)(g_Xbuf + ((size_t)e * CAP + s) * DDIM);
        for (int i = threadIdx.x; i < DDIM / 4; i += blockDim.x) {
            float4 v = src[i];
            dst[i * 2]     = __floats2half2_rn(v.x, v.y);
            dst[i * 2 + 1] = __floats2half2_rn(v.z, v.w);
        }
    } else {
        float p = g_prob[t];
        float4* dst = (float4*)(out + (size_t)t * DDIM);
        for (int i = threadIdx.x; i < DDIM / 4; i += blockDim.x) {
            float4 v = src[i];
            v.x *= p; v.y *= p; v.z *= p; v.w *= p;
            dst[i] = v;
        }
    }
}

// ===================== GEMM core =====================
// CTA tile 128x128, K-chunk 64, 128 threads = 4 warps in 2(M) x 2(N),
// warp tile 64x64. 3 stages: A @ s*16KB, B @ 48KB + s*16KB. 96KB total.
// cp.async for chunk k+2 is DRIP-FED between the MMA bursts of chunk k so the
// LDGSTS dispatch floor (8 cyc/op/SMSP) hides under the HMMA pipe shadow.
constexpr int SMEM_A_STAGE = 16384;
constexpr int SMEM_B_BASE  = 49152;
constexpr int SMEM_B_STAGE = 16384;
constexpr int SMEM_BYTES   = 98304;

__device__ __forceinline__ void issue_chunk(const __half* Ak, const __half* Bk,
                                            int ld, uint32_t sb, int stage, int tid) {
    uint32_t abase = sb + stage * SMEM_A_STAGE;
    uint32_t bbase = sb + SMEM_B_BASE + stage * SMEM_B_STAGE;
#pragma unroll
    for (int it = 0; it < 8; ++it) {
        int u = it * 128 + tid;
        int row = u >> 3, seg = u & 7;
        CP_ASYNC16(abase + SMEM_SWIZZLE_128B(row * 128 + seg * 16),
                   (const char*)(Ak + (size_t)row * ld) + seg * 16);
    }
#pragma unroll
    for (int it = 0; it < 8; ++it) {
        int u = it * 128 + tid;
        int row = u >> 3, seg = u & 7;
        CP_ASYNC16(bbase + SMEM_SWIZZLE_128B(row * 128 + seg * 16),
                   (const char*)(Bk + (size_t)row * ld) + seg * 16);
    }
}

// 4 cp.asyncs (2 A-rows-worth + 2 B) for drip group `g` (0..3)
__device__ __forceinline__ void drip_group(int g, const __half* Ak, const __half* Bk,
                                           int ld, uint32_t abase, uint32_t bbase,
                                           int tid) {
#pragma unroll
    for (int j = 0; j < 2; ++j) {
        int u = (g * 2 + j) * 128 + tid;
        int row = u >> 3, seg = u & 7;
        CP_ASYNC16(abase + SMEM_SWIZZLE_128B(row * 128 + seg * 16),
                   (const char*)(Ak + (size_t)row * ld) + seg * 16);
        CP_ASYNC16(bbase + SMEM_SWIZZLE_128B(row * 128 + seg * 16),
                   (const char*)(Bk + (size_t)row * ld) + seg * 16);
    }
}

__device__ __forceinline__ void load_frags(uint32_t abase, uint32_t bbase,
                                           int wm, int wn, int lane, int ks,
                                           uint32_t af[4][4], uint32_t bf[8][2]) {
#pragma unroll
    for (int mt = 0; mt < 4; ++mt) {
        int row = wm * 64 + mt * 16 + (lane & 15);
        int colb = ks * 32 + (lane >> 4) * 16;
        ldsm_x4(af[mt][0], af[mt][1], af[mt][2], af[mt][3],
                abase + SMEM_SWIZZLE_128B(row * 128 + colb));
    }
#pragma unroll
    for (int np = 0; np < 4; ++np) {
        int nrow = wn * 64 + np * 16 + (lane >> 4) * 8 + (lane & 7);
        int colb = ks * 32 + ((lane >> 3) & 1) * 16;
        uint32_t r0, r1, r2, r3;
        ldsm_x4(r0, r1, r2, r3, bbase + SMEM_SWIZZLE_128B(nrow * 128 + colb));
        bf[np * 2][0] = r0;     bf[np * 2][1] = r1;
        bf[np * 2 + 1][0] = r2; bf[np * 2 + 1][1] = r3;
    }
}

__device__ __forceinline__ void compute_chunk_drip(
    uint32_t abase, uint32_t bbase,          // current stage (consume)
    uint32_t nabase, uint32_t nbbase,        // stage for chunk k+2 (produce)
    const __half* An, const __half* Bn,      // gmem for chunk k+2
    int ld, bool drip, int tid,
    int wm, int wn, int lane, float acc[4][8][4])
{
    uint32_t af[2][4][4], bf[2][8][2];
    load_frags(abase, bbase, wm, wn, lane, 0, af[0], bf[0]);
#pragma unroll
    for (int ks = 0; ks < 4; ++ks) {
        int cur = ks & 1;
        if (ks < 3)
            load_frags(abase, bbase, wm, wn, lane, ks + 1, af[cur ^ 1], bf[cur ^ 1]);
        if (drip)
            drip_group(ks, An, Bn, ld, nabase, nbbase, tid);
#pragma unroll
        for (int mt = 0; mt < 4; ++mt)
#pragma unroll
            for (int nt = 0; nt < 8; ++nt)
                mma16816(acc[mt][nt], af[cur][mt], bf[cur][nt]);
    }
}

__device__ __forceinline__ void gemm_mainloop(int nk, const __half* Ab, const __half* Bb,
                                              int ld, uint32_t sb, int tid,
                                              int wm, int wn, int lane,
                                              float acc[4][8][4]) {
    issue_chunk(Ab, Bb, ld, sb, 0, tid);
    CP_COMMIT();
    issue_chunk(Ab + 64, Bb + 64, ld, sb, 1, tid);
    CP_COMMIT();
    for (int kc = 0; kc < nk; ++kc) {
        if (kc + 1 < nk) { CP_WAIT(1); } else { CP_WAIT(0); }
        __syncthreads();
        bool drip = (kc + 2 < nk);
        int ns = (kc + 2) % 3;
        compute_chunk_drip(sb + (kc % 3) * SMEM_A_STAGE,
                           sb + SMEM_B_BASE + (kc % 3) * SMEM_B_STAGE,
                           sb + ns * SMEM_A_STAGE,
                           sb + SMEM_B_BASE + ns * SMEM_B_STAGE,
                           Ab + (size_t)(kc + 2) * 64, Bb + (size_t)(kc + 2) * 64,
                           ld, drip, tid, wm, wn, lane, acc);
        if (drip) CP_COMMIT();
    }
}

__device__ __forceinline__ float gelu_exact(float v) {
    return 0.5f * v * (1.0f + erff(v * 0.70710678118654752f));
}

// ===================== GEMM1: H = gelu(Xbuf @ w1t^T + b1) =====================
// grid: (FDIM/128=24, CAP/128=20, E=8), 128 threads
__global__ void __launch_bounds__(128, 2) gemm1_kernel(const float* __restrict__ b1) {
    extern __shared__ char smem[];
    uint32_t sb = smem_u32(smem);
    int tid = threadIdx.x, lane = tid & 31, w = tid >> 5;
    int wm = w & 1, wn = w >> 1;
    int e = blockIdx.z, m0 = blockIdx.y * 128, f0 = blockIdx.x * 128;
    int cnt = g_cnt[e];
    int mcnt = cnt < CAP ? cnt : CAP;
    if (m0 >= mcnt) return;

    float acc[4][8][4];
#pragma unroll
    for (int a = 0; a < 4; a++)
#pragma unroll
        for (int b = 0; b < 8; b++)
#pragma unroll
            for (int c = 0; c < 4; c++) acc[a][b][c] = 0.f;

    const __half* Ab = g_Xbuf + ((size_t)e * CAP + m0) * DDIM;
    const __half* Bb = g_w1t + (size_t)e * FDIM * DDIM + (size_t)f0 * DDIM;
    gemm_mainloop(DDIM / 64, Ab, Bb, DDIM, sb, tid, wm, wn, lane, acc);

    // epilogue: + bias, exact GELU, fp16 store
    const float* bb = b1 + (size_t)e * FDIM + f0 + wn * 64;
    __half* Hb = g_H + ((size_t)e * CAP + m0) * FDIM + f0;
    int lq = lane >> 2, lr = lane & 3;
#pragma unroll
    for (int nt = 0; nt < 8; ++nt) {
        float bc0 = bb[nt * 8 + lr * 2];
        float bc1 = bb[nt * 8 + lr * 2 + 1];
        int col = wn * 64 + nt * 8 + lr * 2;
#pragma unroll
        for (int mt = 0; mt < 4; ++mt) {
            int r0 = wm * 64 + mt * 16 + lq;
            __half2 v0 = __floats2half2_rn(gelu_exact(acc[mt][nt][0] + bc0),
                                           gelu_exact(acc[mt][nt][1] + bc1));
            __half2 v1 = __floats2half2_rn(gelu_exact(acc[mt][nt][2] + bc0),
                                           gelu_exact(acc[mt][nt][3] + bc1));
            *(__half2*)(Hb + (size_t)r0 * FDIM + col) = v0;
            *(__half2*)(Hb + (size_t)(r0 + 8) * FDIM + col) = v1;
        }
    }
}

// ===================== GEMM2: out[token] = (H @ w2t^T + b2) * prob ============
// grid: (DDIM/128=6, CAP/128=20, E=8), 128 threads
__global__ void __launch_bounds__(128, 2) gemm2_kernel(const float* __restrict__ b2,
                                                       float* __restrict__ out) {
    extern __shared__ char smem[];
    uint32_t sb = smem_u32(smem);
    int tid = threadIdx.x, lane = tid & 31, w = tid >> 5;
    int wm = w & 1, wn = w >> 1;
    int e = blockIdx.z, m0 = blockIdx.y * 128, n0 = blockIdx.x * 128;
    int cnt = g_cnt[e];
    int mcnt = cnt < CAP ? cnt : CAP;
    if (m0 >= mcnt) return;

    float acc[4][8][4];
#pragma unroll
    for (int a = 0; a < 4; a++)
#pragma unroll
        for (int b = 0; b < 8; b++)
#pragma unroll
            for (int c = 0; c < 4; c++) acc[a][b][c] = 0.f;

    const __half* Ab = g_H + ((size_t)e * CAP + m0) * FDIM;
    const __half* Bb = g_w2t + (size_t)e * DDIM * FDIM + (size_t)n0 * FDIM;
    gemm_mainloop(FDIM / 64, Ab, Bb, FDIM, sb, tid, wm, wn, lane, acc);

    // epilogue: + bias, * prob, scatter rows to tokens
    const float* bb = b2 + (size_t)e * DDIM + n0 + wn * 64;
    int lq = lane >> 2, lr = lane & 3;
    float bc0[8], bc1[8];
#pragma unroll
    for (int nt = 0; nt < 8; ++nt) {
        bc0[nt] = bb[nt * 8 + lr * 2];
        bc1[nt] = bb[nt * 8 + lr * 2 + 1];
    }
#pragma unroll
    for (int mt = 0; mt < 4; ++mt) {
#pragma unroll
        for (int half = 0; half < 2; ++half) {
            int row = wm * 64 + mt * 16 + lq + half * 8;
            int gm = m0 + row;
            if (gm < mcnt) {
                int tok = g_tok[e * CAP + gm];
                float p = g_prob[tok];
                float* orow = out + (size_t)tok * DDIM + n0 + wn * 64;
#pragma unroll
                for (int nt = 0; nt < 8; ++nt) {
                    float2 v;
                    v.x = (acc[mt][nt][half * 2]     + bc0[nt]) * p;
                    v.y = (acc[mt][nt][half * 2 + 1] + bc1[nt]) * p;
                    *(float2*)(orow + nt * 8 + lr * 2) = v;
                }
            }
        }
    }
}

// ===================== launch =====================
extern "C" void kernel_launch(void* const* d_in, const int* in_sizes, int n_in,
                              void* d_out, int out_size) {
    const float* x   = (const float*)d_in[0];
    const float* sw  = (const float*)d_in[1];
    const float* sbv = (const float*)d_in[2];
    const float* w1  = (const float*)d_in[3];
    const float* b1  = (const float*)d_in[4];
    const float* w2  = (const float*)d_in[5];
    const float* b2  = (const float*)d_in[6];
    float* out = (float*)d_out;

    cudaFuncSetAttribute(gemm1_kernel, cudaFuncAttributeMaxDynamicSharedMemorySize, SMEM_BYTES);
    cudaFuncSetAttribute(gemm2_kernel, cudaFuncAttributeMaxDynamicSharedMemorySize, SMEM_BYTES);

    zero_cnt_kernel<<<1, 32>>>();
    prep_kernel<<<PREP_BLOCKS, 256>>>(x, sw, sbv, w1, w2);
    gather_kernel<<<NTOK, 192>>>(x, out);
    gemm1_kernel<<<dim3(FDIM / 128, CAP / 128, NEXP), 128, SMEM_BYTES>>>(b1);
    gemm2_kernel<<<dim3(DDIM / 128, CAP / 128, NEXP), 128, SMEM_BYTES>>>(b2, out);
}

// round 9
// speedup vs baseline: 1.4196x; 1.4196x over previous
#include <cuda_runtime.h>
#include <cuda_fp16.h>
#include <cstdint>

// ===================== problem constants =====================
constexpr int NTOK = 16384;     // 8*2048
constexpr int DDIM = 768;
constexpr int FDIM = 3072;
constexpr int NEXP = 8;
constexpr int CAP  = 2560;      // int(1.25*16384/8)

// ===================== device scratch (static; allocation-free) ==============
__device__ __half g_Xbuf[(size_t)NEXP * CAP * DDIM];   // [E][CAP][D] fp16
__device__ __half g_H   [(size_t)NEXP * CAP * FDIM];   // [E][CAP][F] fp16
__device__ __half g_w1t [(size_t)NEXP * FDIM * DDIM];  // [E][F][D] K-major fp16
__device__ __half g_w2t [(size_t)NEXP * DDIM * FDIM];  // [E][D][F] K-major fp16
__device__ int    g_route[NTOK];
__device__ float  g_prob [NTOK];
__device__ int    g_slot [NTOK];
__device__ int    g_tok  [NEXP * CAP];
__device__ int    g_cnt  [16];

// ===================== PTX helpers (sm_80-era, compute_103-safe) =============
__device__ __forceinline__ uint32_t smem_u32(const void* p) {
    uint32_t a;
    asm("{ .reg .u64 t; cvta.to.shared.u64 t, %1; cvt.u32.u64 %0, t; }"
        : "=r"(a) : "l"(p));
    return a;
}

#define CP_ASYNC16(dst_smem, src_gmem) \
    asm volatile("cp.async.cg.shared.global [%0], [%1], 16;" \
        :: "r"(dst_smem), "l"(src_gmem))
#define CP_COMMIT() asm volatile("cp.async.commit_group;" ::: "memory")
#define CP_WAIT(n)  asm volatile("cp.async.wait_group %0;" :: "n"(n) : "memory")

__device__ __forceinline__ void ldsm_x4(uint32_t& r0, uint32_t& r1,
                                        uint32_t& r2, uint32_t& r3, uint32_t addr) {
    asm volatile("ldmatrix.sync.aligned.m8n8.x4.shared.b16 {%0,%1,%2,%3}, [%4];"
        : "=r"(r0), "=r"(r1), "=r"(r2), "=r"(r3) : "r"(addr));
}

__device__ __forceinline__ void mma16816(float* d, const uint32_t* a, const uint32_t* b) {
    asm volatile(
        "mma.sync.aligned.m16n8k16.row.col.f32.f16.f16.f32 "
        "{%0,%1,%2,%3}, {%4,%5,%6,%7}, {%8,%9}, {%0,%1,%2,%3};"
        : "+f"(d[0]), "+f"(d[1]), "+f"(d[2]), "+f"(d[3])
        : "r"(a[0]), "r"(a[1]), "r"(a[2]), "r"(a[3]), "r"(b[0]), "r"(b[1]));
}

#define SMEM_SWIZZLE_128B(off) ((off) ^ (((off) >> 3) & 0x70))

// ===================== prep kernel: transposes + router fused ================
__global__ void zero_cnt_kernel() {
    if (threadIdx.x < 16) g_cnt[threadIdx.x] = 0;
}

constexpr int PREP_W1 = (FDIM / 32) * (DDIM / 32) * NEXP;   // 18432
constexpr int PREP_W2 = (DDIM / 32) * (FDIM / 32) * NEXP;   // 18432
constexpr int PREP_RT = NTOK / 16;                          // 1024
constexpr int PREP_BLOCKS = PREP_W1 + PREP_W2 + PREP_RT;

__device__ __forceinline__ void transpose_block(const float* __restrict__ in,
                                                __half* __restrict__ outp,
                                                int R, int C, int e, int cx, int ry,
                                                float tile[32][33]) {
    int c0 = cx * 32, r0 = ry * 32;
    const float* inp = in + (size_t)e * R * C;
    __half* op = outp + (size_t)e * R * C;
    int tx = threadIdx.x & 31, ty = threadIdx.x >> 5;
#pragma unroll
    for (int k = 0; k < 32; k += 8)
        tile[ty + k][tx] = inp[(size_t)(r0 + ty + k) * C + c0 + tx];
    __syncthreads();
#pragma unroll
    for (int k = 0; k < 32; k += 8)
        op[(size_t)(c0 + ty + k) * R + r0 + tx] = __float2half(tile[tx][ty + k]);
}

__device__ __forceinline__ void router_block(const float* __restrict__ x,
                                             const float* __restrict__ sw,
                                             const float* __restrict__ sb,
                                             int rb) {
    int w = rb * 8 + ((int)threadIdx.x >> 5);
    int lane = threadIdx.x & 31;
    int t0 = w * 2;
    const float* x0 = x + (size_t)t0 * DDIM;
    const float* x1 = x0 + DDIM;
    float a0[8], a1[8];
#pragma unroll
    for (int e = 0; e < 8; e++) { a0[e] = 0.f; a1[e] = 0.f; }
    for (int d = lane; d < DDIM; d += 32) {
        float xv0 = x0[d], xv1 = x1[d];
        const float4* wr = (const float4*)(sw + (size_t)d * 8);
        float4 w0 = wr[0], w1 = wr[1];
        a0[0] += xv0 * w0.x; a0[1] += xv0 * w0.y;
        a0[2] += xv0 * w0.z; a0[3] += xv0 * w0.w;
        a0[4] += xv0 * w1.x; a0[5] += xv0 * w1.y;
        a0[6] += xv0 * w1.z; a0[7] += xv0 * w1.w;
        a1[0] += xv1 * w0.x; a1[1] += xv1 * w0.y;
        a1[2] += xv1 * w0.z; a1[3] += xv1 * w0.w;
        a1[4] += xv1 * w1.x; a1[5] += xv1 * w1.y;
        a1[6] += xv1 * w1.z; a1[7] += xv1 * w1.w;
    }
#pragma unroll
    for (int off = 16; off; off >>= 1) {
#pragma unroll
        for (int e = 0; e < 8; e++) {
            a0[e] += __shfl_xor_sync(0xFFFFFFFFu, a0[e], off);
            a1[e] += __shfl_xor_sync(0xFFFFFFFFu, a1[e], off);
        }
    }
    if (lane == 0) {
#pragma unroll
        for (int pair = 0; pair < 2; ++pair) {
            float* acc = pair ? a1 : a0;
            int t = t0 + pair;
            float l[8];
            float best = -1e30f; int be = 0;
#pragma unroll
            for (int e = 0; e < 8; e++) {
                l[e] = acc[e] + sb[e];
                if (l[e] > best) { best = l[e]; be = e; }
            }
            float s = 0.f;
#pragma unroll
            for (int e = 0; e < 8; e++) s += expf(l[e] - best);
            float p = 1.0f / s;
            g_route[t] = be;
            g_prob[t] = p;
            int slot = atomicAdd(&g_cnt[be], 1);
            g_slot[t] = slot;
            if (slot < CAP) g_tok[be * CAP + slot] = t;
        }
    }
}

__global__ void __launch_bounds__(256) prep_kernel(const float* __restrict__ x,
                                                   const float* __restrict__ sw,
                                                   const float* __restrict__ sb,
                                                   const float* __restrict__ w1,
                                                   const float* __restrict__ w2) {
    __shared__ float tile[32][33];
    int b = blockIdx.x;
    if (b < PREP_W1) {
        int e = b / ((FDIM / 32) * (DDIM / 32));
        int rem = b % ((FDIM / 32) * (DDIM / 32));
        int cx = rem % (FDIM / 32), ry = rem / (FDIM / 32);
        transpose_block(w1, g_w1t, DDIM, FDIM, e, cx, ry, tile);
    } else if (b < PREP_W1 + PREP_W2) {
        int bb = b - PREP_W1;
        int e = bb / ((DDIM / 32) * (FDIM / 32));
        int rem = bb % ((DDIM / 32) * (FDIM / 32));
        int cx = rem % (DDIM / 32), ry = rem / (DDIM / 32);
        transpose_block(w2, g_w2t, FDIM, DDIM, e, cx, ry, tile);
    } else {
        router_block(x, sw, sb, b - PREP_W1 - PREP_W2);
    }
}

// gather + passthrough fused
__global__ void gather_kernel(const float* __restrict__ x, float* __restrict__ out) {
    int t = blockIdx.x;
    int e = g_route[t];
    int s = g_slot[t];
    const float4* src = (const float4*)(x + (size_t)t * DDIM);
    if (s < CAP) {
        __half2* dst = (__half2*)(g_Xbuf + ((size_t)e * CAP + s) * DDIM);
        for (int i = threadIdx.x; i < DDIM / 4; i += blockDim.x) {
            float4 v = src[i];
            dst[i * 2]     = __floats2half2_rn(v.x, v.y);
            dst[i * 2 + 1] = __floats2half2_rn(v.z, v.w);
        }
    } else {
        float p = g_prob[t];
        float4* dst = (float4*)(out + (size_t)t * DDIM);
        for (int i = threadIdx.x; i < DDIM / 4; i += blockDim.x) {
            float4 v = src[i];
            v.x *= p; v.y *= p; v.z *= p; v.w *= p;
            dst[i] = v;
        }
    }
}

// ===================== GEMM core (R3 structure — best measured) ==============
// CTA tile 128x128, K-chunk 64, 256 threads = 8 warps in 4(M) x 2(N),
// warp tile 32x64. 2 stages: A bufs @ 0/16K, B bufs @ 32K/48K. 64KB total.
__device__ __forceinline__ void issue_chunk(const __half* Ak, const __half* Bk,
                                            int ld, uint32_t sb, int buf, int tid) {
    uint32_t abase = sb + buf * 16384;
    uint32_t bbase = sb + 32768 + buf * 16384;
#pragma unroll
    for (int it = 0; it < 8; ++it) {
        int u = it * 256 + tid;
        int v = u & 1023;
        int row = v >> 3, seg = v & 7;
        const void* src = (const char*)((u < 1024 ? Ak : Bk) + (size_t)row * ld) + seg * 16;
        uint32_t dst = (u < 1024 ? abase : bbase) + SMEM_SWIZZLE_128B(row * 128 + seg * 16);
        CP_ASYNC16(dst, src);
    }
}

__device__ __forceinline__ void compute_chunk(uint32_t abase, uint32_t bbase,
                                              int wm, int wn, int lane,
                                              float acc[2][8][4]) {
#pragma unroll
    for (int ks = 0; ks < 4; ++ks) {
        uint32_t af[2][4];
#pragma unroll
        for (int mt = 0; mt < 2; ++mt) {
            int row = wm * 32 + mt * 16 + (lane & 15);
            int colb = ks * 32 + (lane >> 4) * 16;
            ldsm_x4(af[mt][0], af[mt][1], af[mt][2], af[mt][3],
                    abase + SMEM_SWIZZLE_128B(row * 128 + colb));
        }
        uint32_t bf[8][2];
#pragma unroll
        for (int np = 0; np < 4; ++np) {
            int nrow = wn * 64 + np * 16 + (lane >> 4) * 8 + (lane & 7);
            int colb = ks * 32 + ((lane >> 3) & 1) * 16;
            uint32_t r0, r1, r2, r3;
            ldsm_x4(r0, r1, r2, r3, bbase + SMEM_SWIZZLE_128B(nrow * 128 + colb));
            bf[np * 2][0] = r0;     bf[np * 2][1] = r1;
            bf[np * 2 + 1][0] = r2; bf[np * 2 + 1][1] = r3;
        }
#pragma unroll
        for (int mt = 0; mt < 2; ++mt)
#pragma unroll
            for (int nt = 0; nt < 8; ++nt)
                mma16816(acc[mt][nt], af[mt], bf[nt]);
    }
}

__device__ __forceinline__ void gemm_mainloop(int nk, const __half* Ab, const __half* Bb,
                                              int ld, uint32_t sb, int tid,
                                              int wm, int wn, int lane,
                                              float acc[2][8][4]) {
    issue_chunk(Ab, Bb, ld, sb, 0, tid);
    CP_COMMIT();
    for (int kc = 0; kc < nk; ++kc) {
        if (kc + 1 < nk) {
            issue_chunk(Ab + (kc + 1) * 64, Bb + (kc + 1) * 64, ld, sb, (kc + 1) & 1, tid);
            CP_COMMIT();
            CP_WAIT(1);
        } else {
            CP_WAIT(0);
        }
        __syncthreads();
        compute_chunk(sb + (kc & 1) * 16384, sb + 32768 + (kc & 1) * 16384,
                      wm, wn, lane, acc);
        __syncthreads();
    }
}

__device__ __forceinline__ float gelu_exact(float v) {
    return 0.5f * v * (1.0f + erff(v * 0.70710678118654752f));
}

// ===================== GEMM1: H = gelu(Xbuf @ w1t^T + b1) =====================
// grid: (FDIM/128=24, CAP/128=20, E=8), 256 threads
__global__ void __launch_bounds__(256) gemm1_kernel(const float* __restrict__ b1) {
    extern __shared__ char smem[];
    uint32_t sb = smem_u32(smem);
    int tid = threadIdx.x, lane = tid & 31, w = tid >> 5;
    int wm = w & 3, wn = w >> 2;
    int e = blockIdx.z, m0 = blockIdx.y * 128, f0 = blockIdx.x * 128;
    int cnt = g_cnt[e];
    int mcnt = cnt < CAP ? cnt : CAP;
    if (m0 >= mcnt) return;

    float acc[2][8][4];
#pragma unroll
    for (int a = 0; a < 2; a++)
#pragma unroll
        for (int b = 0; b < 8; b++)
#pragma unroll
            for (int c = 0; c < 4; c++) acc[a][b][c] = 0.f;

    const __half* Ab = g_Xbuf + ((size_t)e * CAP + m0) * DDIM;
    const __half* Bb = g_w1t + (size_t)e * FDIM * DDIM + (size_t)f0 * DDIM;
    gemm_mainloop(DDIM / 64, Ab, Bb, DDIM, sb, tid, wm, wn, lane, acc);

    // epilogue: + bias, exact GELU, fp16 store
    const float* bb = b1 + (size_t)e * FDIM + f0 + wn * 64;
    __half* Hb = g_H + ((size_t)e * CAP + m0) * FDIM + f0;
    int lq = lane >> 2, lr = lane & 3;
#pragma unroll
    for (int nt = 0; nt < 8; ++nt) {
        float bc0 = bb[nt * 8 + lr * 2];
        float bc1 = bb[nt * 8 + lr * 2 + 1];
        int col = wn * 64 + nt * 8 + lr * 2;
#pragma unroll
        for (int mt = 0; mt < 2; ++mt) {
            int r0 = wm * 32 + mt * 16 + lq;
            __half2 v0 = __floats2half2_rn(gelu_exact(acc[mt][nt][0] + bc0),
                                           gelu_exact(acc[mt][nt][1] + bc1));
            __half2 v1 = __floats2half2_rn(gelu_exact(acc[mt][nt][2] + bc0),
                                           gelu_exact(acc[mt][nt][3] + bc1));
            *(__half2*)(Hb + (size_t)r0 * FDIM + col) = v0;
            *(__half2*)(Hb + (size_t)(r0 + 8) * FDIM + col) = v1;
        }
    }
}

// ===================== GEMM2: out[token] = (H @ w2t^T + b2) * prob ============
// grid: (DDIM/128=6, CAP/128=20, E=8), 256 threads
__global__ void __launch_bounds__(256) gemm2_kernel(const float* __restrict__ b2,
                                                    float* __restrict__ out) {
    extern __shared__ char smem[];
    uint32_t sb = smem_u32(smem);
    int tid = threadIdx.x, lane = tid & 31, w = tid >> 5;
    int wm = w & 3, wn = w >> 2;
    int e = blockIdx.z, m0 = blockIdx.y * 128, n0 = blockIdx.x * 128;
    int cnt = g_cnt[e];
    int mcnt = cnt < CAP ? cnt : CAP;
    if (m0 >= mcnt) return;

    float acc[2][8][4];
#pragma unroll
    for (int a = 0; a < 2; a++)
#pragma unroll
        for (int b = 0; b < 8; b++)
#pragma unroll
            for (int c = 0; c < 4; c++) acc[a][b][c] = 0.f;

    const __half* Ab = g_H + ((size_t)e * CAP + m0) * FDIM;
    const __half* Bb = g_w2t + (size_t)e * DDIM * FDIM + (size_t)n0 * FDIM;
    gemm_mainloop(FDIM / 64, Ab, Bb, FDIM, sb, tid, wm, wn, lane, acc);

    // epilogue: + bias, * prob, scatter rows to tokens
    const float* bb = b2 + (size_t)e * DDIM + n0 + wn * 64;
    int lq = lane >> 2, lr = lane & 3;
    float bc0[8], bc1[8];
#pragma unroll
    for (int nt = 0; nt < 8; ++nt) {
        bc0[nt] = bb[nt * 8 + lr * 2];
        bc1[nt] = bb[nt * 8 + lr * 2 + 1];
    }
#pragma unroll
    for (int mt = 0; mt < 2; ++mt) {
#pragma unroll
        for (int half = 0; half < 2; ++half) {
            int row = wm * 32 + mt * 16 + lq + half * 8;
            int gm = m0 + row;
            if (gm < mcnt) {
                int tok = g_tok[e * CAP + gm];
                float p = g_prob[tok];
                float* orow = out + (size_t)tok * DDIM + n0 + wn * 64;
#pragma unroll
                for (int nt = 0; nt < 8; ++nt) {
                    float2 v;
                    v.x = (acc[mt][nt][half * 2]     + bc0[nt]) * p;
                    v.y = (acc[mt][nt][half * 2 + 1] + bc1[nt]) * p;
                    *(float2*)(orow + nt * 8 + lr * 2) = v;
                }
            }
        }
    }
}

// ===================== launch =====================
extern "C" void kernel_launch(void* const* d_in, const int* in_sizes, int n_in,
                              void* d_out, int out_size) {
    const float* x   = (const float*)d_in[0];
    const float* sw  = (const float*)d_in[1];
    const float* sbv = (const float*)d_in[2];
    const float* w1  = (const float*)d_in[3];
    const float* b1  = (const float*)d_in[4];
    const float* w2  = (const float*)d_in[5];
    const float* b2  = (const float*)d_in[6];
    float* out = (float*)d_out;

    const int SMEM_BYTES = 65536;
    cudaFuncSetAttribute(gemm1_kernel, cudaFuncAttributeMaxDynamicSharedMemorySize, SMEM_BYTES);
    cudaFuncSetAttribute(gemm2_kernel, cudaFuncAttributeMaxDynamicSharedMemorySize, SMEM_BYTES);

    zero_cnt_kernel<<<1, 32>>>();
    prep_kernel<<<PREP_BLOCKS, 256>>>(x, sw, sbv, w1, w2);
    gather_kernel<<<NTOK, 192>>>(x, out);
    gemm1_kernel<<<dim3(FDIM / 128, CAP / 128, NEXP), 256, SMEM_BYTES>>>(b1);
    gemm2_kernel<<<dim3(DDIM / 128, CAP / 128, NEXP), 256, SMEM_BYTES>>>(b2, out);
}

// round 10
// speedup vs baseline: 1.4371x; 1.0124x over previous
#include <cuda_runtime.h>
#include <cuda_fp16.h>
#include <cstdint>

// ===================== problem constants =====================
constexpr int NTOK = 16384;     // 8*2048
constexpr int DDIM = 768;
constexpr int FDIM = 3072;
constexpr int NEXP = 8;
constexpr int CAP  = 2560;      // int(1.25*16384/8)

// ===================== device scratch (static; allocation-free) ==============
__device__ __half g_Xbuf[(size_t)NEXP * CAP * DDIM];   // [E][CAP][D] fp16
__device__ __half g_H   [(size_t)NEXP * CAP * FDIM];   // [E][CAP][F] fp16
__device__ __half g_w1t [(size_t)NEXP * FDIM * DDIM];  // [E][F][D] K-major fp16
__device__ __half g_w2t [(size_t)NEXP * DDIM * FDIM];  // [E][D][F] K-major fp16
__device__ int    g_route[NTOK];
__device__ float  g_prob [NTOK];
__device__ int    g_slot [NTOK];
__device__ int    g_tok  [NEXP * CAP];
__device__ int    g_cnt  [16];

// ===================== PTX helpers (sm_80-era, compute_103-safe) =============
__device__ __forceinline__ uint32_t smem_u32(const void* p) {
    uint32_t a;
    asm("{ .reg .u64 t; cvta.to.shared.u64 t, %1; cvt.u32.u64 %0, t; }"
        : "=r"(a) : "l"(p));
    return a;
}

#define CP_ASYNC16(dst_smem, src_gmem) \
    asm volatile("cp.async.cg.shared.global [%0], [%1], 16;" \
        :: "r"(dst_smem), "l"(src_gmem))
#define CP_COMMIT() asm volatile("cp.async.commit_group;" ::: "memory")
#define CP_WAIT(n)  asm volatile("cp.async.wait_group %0;" :: "n"(n) : "memory")

__device__ __forceinline__ void ldsm_x4(uint32_t& r0, uint32_t& r1,
                                        uint32_t& r2, uint32_t& r3, uint32_t addr) {
    asm volatile("ldmatrix.sync.aligned.m8n8.x4.shared.b16 {%0,%1,%2,%3}, [%4];"
        : "=r"(r0), "=r"(r1), "=r"(r2), "=r"(r3) : "r"(addr));
}

__device__ __forceinline__ void mma16816(float* d, const uint32_t* a, const uint32_t* b) {
    asm volatile(
        "mma.sync.aligned.m16n8k16.row.col.f32.f16.f16.f32 "
        "{%0,%1,%2,%3}, {%4,%5,%6,%7}, {%8,%9}, {%0,%1,%2,%3};"
        : "+f"(d[0]), "+f"(d[1]), "+f"(d[2]), "+f"(d[3])
        : "r"(a[0]), "r"(a[1]), "r"(a[2]), "r"(a[3]), "r"(b[0]), "r"(b[1]));
}

#define SMEM_SWIZZLE_128B(off) ((off) ^ (((off) >> 3) & 0x70))

// ===================== prep kernel: transposes + router fused ================
__global__ void zero_cnt_kernel() {
    if (threadIdx.x < 16) g_cnt[threadIdx.x] = 0;
}

constexpr int PREP_W1 = (FDIM / 32) * (DDIM / 32) * NEXP;   // 18432
constexpr int PREP_W2 = (DDIM / 32) * (FDIM / 32) * NEXP;   // 18432
constexpr int PREP_RT = NTOK / 16;                          // 1024
constexpr int PREP_BLOCKS = PREP_W1 + PREP_W2 + PREP_RT;

__device__ __forceinline__ void transpose_block(const float* __restrict__ in,
                                                __half* __restrict__ outp,
                                                int R, int C, int e, int cx, int ry,
                                                float tile[32][33]) {
    int c0 = cx * 32, r0 = ry * 32;
    const float* inp = in + (size_t)e * R * C;
    __half* op = outp + (size_t)e * R * C;
    int tx = threadIdx.x & 31, ty = threadIdx.x >> 5;
#pragma unroll
    for (int k = 0; k < 32; k += 8)
        tile[ty + k][tx] = inp[(size_t)(r0 + ty + k) * C + c0 + tx];
    __syncthreads();
#pragma unroll
    for (int k = 0; k < 32; k += 8)
        op[(size_t)(c0 + ty + k) * R + r0 + tx] = __float2half(tile[tx][ty + k]);
}

__device__ __forceinline__ void router_block(const float* __restrict__ x,
                                             const float* __restrict__ sw,
                                             const float* __restrict__ sb,
                                             int rb) {
    int w = rb * 8 + ((int)threadIdx.x >> 5);
    int lane = threadIdx.x & 31;
    int t0 = w * 2;
    const float* x0 = x + (size_t)t0 * DDIM;
    const float* x1 = x0 + DDIM;
    float a0[8], a1[8];
#pragma unroll
    for (int e = 0; e < 8; e++) { a0[e] = 0.f; a1[e] = 0.f; }
    for (int d = lane; d < DDIM; d += 32) {
        float xv0 = x0[d], xv1 = x1[d];
        const float4* wr = (const float4*)(sw + (size_t)d * 8);
        float4 w0 = wr[0], w1 = wr[1];
        a0[0] += xv0 * w0.x; a0[1] += xv0 * w0.y;
        a0[2] += xv0 * w0.z; a0[3] += xv0 * w0.w;
        a0[4] += xv0 * w1.x; a0[5] += xv0 * w1.y;
        a0[6] += xv0 * w1.z; a0[7] += xv0 * w1.w;
        a1[0] += xv1 * w0.x; a1[1] += xv1 * w0.y;
        a1[2] += xv1 * w0.z; a1[3] += xv1 * w0.w;
        a1[4] += xv1 * w1.x; a1[5] += xv1 * w1.y;
        a1[6] += xv1 * w1.z; a1[7] += xv1 * w1.w;
    }
#pragma unroll
    for (int off = 16; off; off >>= 1) {
#pragma unroll
        for (int e = 0; e < 8; e++) {
            a0[e] += __shfl_xor_sync(0xFFFFFFFFu, a0[e], off);
            a1[e] += __shfl_xor_sync(0xFFFFFFFFu, a1[e], off);
        }
    }
    if (lane == 0) {
#pragma unroll
        for (int pair = 0; pair < 2; ++pair) {
            float* acc = pair ? a1 : a0;
            int t = t0 + pair;
            float l[8];
            float best = -1e30f; int be = 0;
#pragma unroll
            for (int e = 0; e < 8; e++) {
                l[e] = acc[e] + sb[e];
                if (l[e] > best) { best = l[e]; be = e; }
            }
            float s = 0.f;
#pragma unroll
            for (int e = 0; e < 8; e++) s += expf(l[e] - best);
            float p = 1.0f / s;
            g_route[t] = be;
            g_prob[t] = p;
            int slot = atomicAdd(&g_cnt[be], 1);
            g_slot[t] = slot;
            if (slot < CAP) g_tok[be * CAP + slot] = t;
        }
    }
}

__global__ void __launch_bounds__(256) prep_kernel(const float* __restrict__ x,
                                                   const float* __restrict__ sw,
                                                   const float* __restrict__ sb,
                                                   const float* __restrict__ w1,
                                                   const float* __restrict__ w2) {
    __shared__ float tile[32][33];
    int b = blockIdx.x;
    if (b < PREP_W1) {
        int e = b / ((FDIM / 32) * (DDIM / 32));
        int rem = b % ((FDIM / 32) * (DDIM / 32));
        int cx = rem % (FDIM / 32), ry = rem / (FDIM / 32);
        transpose_block(w1, g_w1t, DDIM, FDIM, e, cx, ry, tile);
    } else if (b < PREP_W1 + PREP_W2) {
        int bb = b - PREP_W1;
        int e = bb / ((DDIM / 32) * (FDIM / 32));
        int rem = bb % ((DDIM / 32) * (FDIM / 32));
        int cx = rem % (DDIM / 32), ry = rem / (DDIM / 32);
        transpose_block(w2, g_w2t, FDIM, DDIM, e, cx, ry, tile);
    } else {
        router_block(x, sw, sb, b - PREP_W1 - PREP_W2);
    }
}

// gather + passthrough fused
__global__ void gather_kernel(const float* __restrict__ x, float* __restrict__ out) {
    int t = blockIdx.x;
    int e = g_route[t];
    int s = g_slot[t];
    const float4* src = (const float4*)(x + (size_t)t * DDIM);
    if (s < CAP) {
        __half2* dst = (__half2*)(g_Xbuf + ((size_t)e * CAP + s) * DDIM);
        for (int i = threadIdx.x; i < DDIM / 4; i += blockDim.x) {
            float4 v = src[i];
            dst[i * 2]     = __floats2half2_rn(v.x, v.y);
            dst[i * 2 + 1] = __floats2half2_rn(v.z, v.w);
        }
    } else {
        float p = g_prob[t];
        float4* dst = (float4*)(out + (size_t)t * DDIM);
        for (int i = threadIdx.x; i < DDIM / 4; i += blockDim.x) {
            float4 v = src[i];
            v.x *= p; v.y *= p; v.z *= p; v.w *= p;
            dst[i] = v;
        }
    }
}

// ===================== GEMM core =====================
// CTA tile 64(M) x 128(N), K-chunk 64, 128 threads = 4 warps in 2(M) x 2(N),
// warp tile 32x64 (identical per-warp code to the measured-best R3/R9 core).
// 2 stages: A @ 0/8K (16KB), B @ 16K/32K (32KB). 48KB total -> 4 CTAs/SM.
constexpr int SMEM_A_STAGE = 8192;
constexpr int SMEM_B_BASE  = 16384;
constexpr int SMEM_B_STAGE = 16384;
constexpr int SMEM_BYTES   = 49152;

__device__ __forceinline__ void issue_chunk(const __half* Ak, const __half* Bk,
                                            int ld, uint32_t sb, int buf, int tid) {
    uint32_t abase = sb + buf * SMEM_A_STAGE;
    uint32_t bbase = sb + SMEM_B_BASE + buf * SMEM_B_STAGE;
#pragma unroll
    for (int it = 0; it < 4; ++it) {           // A: 64 rows x 8 segs = 512
        int u = it * 128 + tid;
        int row = u >> 3, seg = u & 7;
        CP_ASYNC16(abase + SMEM_SWIZZLE_128B(row * 128 + seg * 16),
                   (const char*)(Ak + (size_t)row * ld) + seg * 16);
    }
#pragma unroll
    for (int it = 0; it < 8; ++it) {           // B: 128 rows x 8 segs = 1024
        int u = it * 128 + tid;
        int row = u >> 3, seg = u & 7;
        CP_ASYNC16(bbase + SMEM_SWIZZLE_128B(row * 128 + seg * 16),
                   (const char*)(Bk + (size_t)row * ld) + seg * 16);
    }
}

__device__ __forceinline__ void compute_chunk(uint32_t abase, uint32_t bbase,
                                              int wm, int wn, int lane,
                                              float acc[2][8][4]) {
#pragma unroll
    for (int ks = 0; ks < 4; ++ks) {
        uint32_t af[2][4];
#pragma unroll
        for (int mt = 0; mt < 2; ++mt) {
            int row = wm * 32 + mt * 16 + (lane & 15);
            int colb = ks * 32 + (lane >> 4) * 16;
            ldsm_x4(af[mt][0], af[mt][1], af[mt][2], af[mt][3],
                    abase + SMEM_SWIZZLE_128B(row * 128 + colb));
        }
        uint32_t bf[8][2];
#pragma unroll
        for (int np = 0; np < 4; ++np) {
            int nrow = wn * 64 + np * 16 + (lane >> 4) * 8 + (lane & 7);
            int colb = ks * 32 + ((lane >> 3) & 1) * 16;
            uint32_t r0, r1, r2, r3;
            ldsm_x4(r0, r1, r2, r3, bbase + SMEM_SWIZZLE_128B(nrow * 128 + colb));
            bf[np * 2][0] = r0;     bf[np * 2][1] = r1;
            bf[np * 2 + 1][0] = r2; bf[np * 2 + 1][1] = r3;
        }
#pragma unroll
        for (int mt = 0; mt < 2; ++mt)
#pragma unroll
            for (int nt = 0; nt < 8; ++nt)
                mma16816(acc[mt][nt], af[mt], bf[nt]);
    }
}

__device__ __forceinline__ void gemm_mainloop(int nk, const __half* Ab, const __half* Bb,
                                              int ld, uint32_t sb, int tid,
                                              int wm, int wn, int lane,
                                              float acc[2][8][4]) {
    issue_chunk(Ab, Bb, ld, sb, 0, tid);
    CP_COMMIT();
    for (int kc = 0; kc < nk; ++kc) {
        if (kc + 1 < nk) {
            issue_chunk(Ab + (kc + 1) * 64, Bb + (kc + 1) * 64, ld, sb, (kc + 1) & 1, tid);
            CP_COMMIT();
            CP_WAIT(1);
        } else {
            CP_WAIT(0);
        }
        __syncthreads();
        compute_chunk(sb + (kc & 1) * SMEM_A_STAGE,
                      sb + SMEM_B_BASE + (kc & 1) * SMEM_B_STAGE,
                      wm, wn, lane, acc);
        __syncthreads();
    }
}

__device__ __forceinline__ float gelu_exact(float v) {
    return 0.5f * v * (1.0f + erff(v * 0.70710678118654752f));
}

// ===================== GEMM1: H = gelu(Xbuf @ w1t^T + b1) =====================
// grid: (FDIM/128=24, CAP/64=40, E=8), 128 threads, 4 CTAs/SM
__global__ void __launch_bounds__(128, 4) gemm1_kernel(const float* __restrict__ b1) {
    extern __shared__ char smem[];
    uint32_t sb = smem_u32(smem);
    int tid = threadIdx.x, lane = tid & 31, w = tid >> 5;
    int wm = w & 1, wn = w >> 1;
    int e = blockIdx.z, m0 = blockIdx.y * 64, f0 = blockIdx.x * 128;
    int cnt = g_cnt[e];
    int mcnt = cnt < CAP ? cnt : CAP;
    if (m0 >= mcnt) return;

    float acc[2][8][4];
#pragma unroll
    for (int a = 0; a < 2; a++)
#pragma unroll
        for (int b = 0; b < 8; b++)
#pragma unroll
            for (int c = 0; c < 4; c++) acc[a][b][c] = 0.f;

    const __half* Ab = g_Xbuf + ((size_t)e * CAP + m0) * DDIM;
    const __half* Bb = g_w1t + (size_t)e * FDIM * DDIM + (size_t)f0 * DDIM;
    gemm_mainloop(DDIM / 64, Ab, Bb, DDIM, sb, tid, wm, wn, lane, acc);

    // epilogue: + bias, exact GELU, fp16 store
    const float* bb = b1 + (size_t)e * FDIM + f0 + wn * 64;
    __half* Hb = g_H + ((size_t)e * CAP + m0) * FDIM + f0;
    int lq = lane >> 2, lr = lane & 3;
#pragma unroll
    for (int nt = 0; nt < 8; ++nt) {
        float bc0 = bb[nt * 8 + lr * 2];
        float bc1 = bb[nt * 8 + lr * 2 + 1];
        int col = wn * 64 + nt * 8 + lr * 2;
#pragma unroll
        for (int mt = 0; mt < 2; ++mt) {
            int r0 = wm * 32 + mt * 16 + lq;
            __half2 v0 = __floats2half2_rn(gelu_exact(acc[mt][nt][0] + bc0),
                                           gelu_exact(acc[mt][nt][1] + bc1));
            __half2 v1 = __floats2half2_rn(gelu_exact(acc[mt][nt][2] + bc0),
                                           gelu_exact(acc[mt][nt][3] + bc1));
            *(__half2*)(Hb + (size_t)r0 * FDIM + col) = v0;
            *(__half2*)(Hb + (size_t)(r0 + 8) * FDIM + col) = v1;
        }
    }
}

// ===================== GEMM2: out[token] = (H @ w2t^T + b2) * prob ============
// grid: (DDIM/128=6, CAP/64=40, E=8), 128 threads, 4 CTAs/SM
__global__ void __launch_bounds__(128, 4) gemm2_kernel(const float* __restrict__ b2,
                                                       float* __restrict__ out) {
    extern __shared__ char smem[];
    uint32_t sb = smem_u32(smem);
    int tid = threadIdx.x, lane = tid & 31, w = tid >> 5;
    int wm = w & 1, wn = w >> 1;
    int e = blockIdx.z, m0 = blockIdx.y * 64, n0 = blockIdx.x * 128;
    int cnt = g_cnt[e];
    int mcnt = cnt < CAP ? cnt : CAP;
    if (m0 >= mcnt) return;

    float acc[2][8][4];
#pragma unroll
    for (int a = 0; a < 2; a++)
#pragma unroll
        for (int b = 0; b < 8; b++)
#pragma unroll
            for (int c = 0; c < 4; c++) acc[a][b][c] = 0.f;

    const __half* Ab = g_H + ((size_t)e * CAP + m0) * FDIM;
    const __half* Bb = g_w2t + (size_t)e * DDIM * FDIM + (size_t)n0 * FDIM;
    gemm_mainloop(FDIM / 64, Ab, Bb, FDIM, sb, tid, wm, wn, lane, acc);

    // epilogue: + bias, * prob, scatter rows to tokens
    const float* bb = b2 + (size_t)e * DDIM + n0 + wn * 64;
    int lq = lane >> 2, lr = lane & 3;
    float bc0[8], bc1[8];
#pragma unroll
    for (int nt = 0; nt < 8; ++nt) {
        bc0[nt] = bb[nt * 8 + lr * 2];
        bc1[nt] = bb[nt * 8 + lr * 2 + 1];
    }
#pragma unroll
    for (int mt = 0; mt < 2; ++mt) {
#pragma unroll
        for (int half = 0; half < 2; ++half) {
            int row = wm * 32 + mt * 16 + lq + half * 8;
            int gm = m0 + row;
            if (gm < mcnt) {
                int tok = g_tok[e * CAP + gm];
                float p = g_prob[tok];
                float* orow = out + (size_t)tok * DDIM + n0 + wn * 64;
#pragma unroll
                for (int nt = 0; nt < 8; ++nt) {
                    float2 v;
                    v.x = (acc[mt][nt][half * 2]     + bc0[nt]) * p;
                    v.y = (acc[mt][nt][half * 2 + 1] + bc1[nt]) * p;
                    *(float2*)(orow + nt * 8 + lr * 2) = v;
                }
            }
        }
    }
}

// ===================== launch =====================
extern "C" void kernel_launch(void* const* d_in, const int* in_sizes, int n_in,
                              void* d_out, int out_size) {
    const float* x   = (const float*)d_in[0];
    const float* sw  = (const float*)d_in[1];
    const float* sbv = (const float*)d_in[2];
    const float* w1  = (const float*)d_in[3];
    const float* b1  = (const float*)d_in[4];
    const float* w2  = (const float*)d_in[5];
    const float* b2  = (const float*)d_in[6];
    float* out = (float*)d_out;

    cudaFuncSetAttribute(gemm1_kernel, cudaFuncAttributeMaxDynamicSharedMemorySize, SMEM_BYTES);
    cudaFuncSetAttribute(gemm2_kernel, cudaFuncAttributeMaxDynamicSharedMemorySize, SMEM_BYTES);

    zero_cnt_kernel<<<1, 32>>>();
    prep_kernel<<<PREP_BLOCKS, 256>>>(x, sw, sbv, w1, w2);
    gather_kernel<<<NTOK, 192>>>(x, out);
    gemm1_kernel<<<dim3(FDIM / 128, CAP / 64, NEXP), 128, SMEM_BYTES>>>(b1);
    gemm2_kernel<<<dim3(DDIM / 128, CAP / 64, NEXP), 128, SMEM_BYTES>>>(b2, out);
}

// round 11
// speedup vs baseline: 1.5002x; 1.0439x over previous
#include <cuda_runtime.h>
#include <cuda_fp16.h>
#include <cstdint>

// ===================== problem constants =====================
constexpr int NTOK = 16384;     // 8*2048
constexpr int DDIM = 768;
constexpr int FDIM = 3072;
constexpr int NEXP = 8;
constexpr int CAP  = 2560;      // int(1.25*16384/8)
constexpr int MB   = CAP / 64;  // 40 m-tiles per expert

// ===================== device scratch (static; allocation-free) ==============
__device__ __half g_Xbuf[(size_t)NEXP * CAP * DDIM];   // [E][CAP][D] fp16
__device__ __half g_H   [(size_t)NEXP * CAP * FDIM];   // [E][CAP][F] fp16
__device__ __half g_w1t [(size_t)NEXP * FDIM * DDIM];  // [E][F][D] K-major fp16
__device__ __half g_w2t [(size_t)NEXP * DDIM * FDIM];  // [E][D][F] K-major fp16
__device__ int    g_route[NTOK];
__device__ float  g_prob [NTOK];
__device__ int    g_slot [NTOK];
__device__ int    g_tok  [NEXP * CAP];
__device__ int    g_cnt  [16];
__device__ int    g_dep  [NEXP * MB];   // gemm1->gemm2 dependency counters

// ===================== PTX helpers (sm_80-era, compute_103-safe) =============
__device__ __forceinline__ uint32_t smem_u32(const void* p) {
    uint32_t a;
    asm("{ .reg .u64 t; cvta.to.shared.u64 t, %1; cvt.u32.u64 %0, t; }"
        : "=r"(a) : "l"(p));
    return a;
}

#define CP_ASYNC16(dst_smem, src_gmem) \
    asm volatile("cp.async.cg.shared.global [%0], [%1], 16;" \
        :: "r"(dst_smem), "l"(src_gmem))
#define CP_COMMIT() asm volatile("cp.async.commit_group;" ::: "memory")
#define CP_WAIT(n)  asm volatile("cp.async.wait_group %0;" :: "n"(n) : "memory")

__device__ __forceinline__ void ldsm_x4(uint32_t& r0, uint32_t& r1,
                                        uint32_t& r2, uint32_t& r3, uint32_t addr) {
    asm volatile("ldmatrix.sync.aligned.m8n8.x4.shared.b16 {%0,%1,%2,%3}, [%4];"
        : "=r"(r0), "=r"(r1), "=r"(r2), "=r"(r3) : "r"(addr));
}

__device__ __forceinline__ void mma16816(float* d, const uint32_t* a, const uint32_t* b) {
    asm volatile(
        "mma.sync.aligned.m16n8k16.row.col.f32.f16.f16.f32 "
        "{%0,%1,%2,%3}, {%4,%5,%6,%7}, {%8,%9}, {%0,%1,%2,%3};"
        : "+f"(d[0]), "+f"(d[1]), "+f"(d[2]), "+f"(d[3])
        : "r"(a[0]), "r"(a[1]), "r"(a[2]), "r"(a[3]), "r"(b[0]), "r"(b[1]));
}

#define SMEM_SWIZZLE_128B(off) ((off) ^ (((off) >> 3) & 0x70))

// ===================== zero kernel =====================
__global__ void zero_cnt_kernel() {
    int i = threadIdx.x;
    if (i < 16) g_cnt[i] = 0;
    for (int j = i; j < NEXP * MB; j += blockDim.x) g_dep[j] = 0;
}

// ===================== prep kernel: transposes + router fused ================
// transpose tiles are 64(r) x 32(c): 128B-coalesced loads AND half2 stores.
constexpr int PREP_W1 = (DDIM / 64) * (FDIM / 32) * NEXP;   // 9216
constexpr int PREP_W2 = (FDIM / 64) * (DDIM / 32) * NEXP;   // 9216
constexpr int PREP_RT = NTOK / 16;                          // 1024
constexpr int PREP_BLOCKS = PREP_W1 + PREP_W2 + PREP_RT;

__device__ __forceinline__ void transpose_block64(const float* __restrict__ in,
                                                  __half* __restrict__ outp,
                                                  int R, int C, int e, int cx, int ry,
                                                  float tile[64][33]) {
    int c0 = cx * 32, r0 = ry * 64;
    const float* inp = in + (size_t)e * R * C;
    __half* op = outp + (size_t)e * R * C;
    int tx = threadIdx.x & 31, ty = threadIdx.x >> 5;
#pragma unroll
    for (int k = 0; k < 8; ++k)
        tile[ty + 8 * k][tx] = inp[(size_t)(r0 + ty + 8 * k) * C + c0 + tx];
    __syncthreads();
    int sx = tx, sy = ty;
#pragma unroll
    for (int j = 0; j < 4; ++j) {
        int cl = sy + 8 * j;
        __half2 v = __floats2half2_rn(tile[2 * sx][cl], tile[2 * sx + 1][cl]);
        *(__half2*)(op + (size_t)(c0 + cl) * R + r0 + 2 * sx) = v;
    }
}

__device__ __forceinline__ void router_block(const float* __restrict__ x,
                                             const float* __restrict__ sw,
                                             const float* __restrict__ sb,
                                             int rb) {
    int w = rb * 8 + ((int)threadIdx.x >> 5);
    int lane = threadIdx.x & 31;
    int t0 = w * 2;
    const float* x0 = x + (size_t)t0 * DDIM;
    const float* x1 = x0 + DDIM;
    float a0[8], a1[8];
#pragma unroll
    for (int e = 0; e < 8; e++) { a0[e] = 0.f; a1[e] = 0.f; }
    for (int d = lane; d < DDIM; d += 32) {
        float xv0 = x0[d], xv1 = x1[d];
        const float4* wr = (const float4*)(sw + (size_t)d * 8);
        float4 w0 = wr[0], w1 = wr[1];
        a0[0] += xv0 * w0.x; a0[1] += xv0 * w0.y;
        a0[2] += xv0 * w0.z; a0[3] += xv0 * w0.w;
        a0[4] += xv0 * w1.x; a0[5] += xv0 * w1.y;
        a0[6] += xv0 * w1.z; a0[7] += xv0 * w1.w;
        a1[0] += xv1 * w0.x; a1[1] += xv1 * w0.y;
        a1[2] += xv1 * w0.z; a1[3] += xv1 * w0.w;
        a1[4] += xv1 * w1.x; a1[5] += xv1 * w1.y;
        a1[6] += xv1 * w1.z; a1[7] += xv1 * w1.w;
    }
#pragma unroll
    for (int off = 16; off; off >>= 1) {
#pragma unroll
        for (int e = 0; e < 8; e++) {
            a0[e] += __shfl_xor_sync(0xFFFFFFFFu, a0[e], off);
            a1[e] += __shfl_xor_sync(0xFFFFFFFFu, a1[e], off);
        }
    }
    if (lane == 0) {
#pragma unroll
        for (int pair = 0; pair < 2; ++pair) {
            float* acc = pair ? a1 : a0;
            int t = t0 + pair;
            float l[8];
            float best = -1e30f; int be = 0;
#pragma unroll
            for (int e = 0; e < 8; e++) {
                l[e] = acc[e] + sb[e];
                if (l[e] > best) { best = l[e]; be = e; }
            }
            float s = 0.f;
#pragma unroll
            for (int e = 0; e < 8; e++) s += expf(l[e] - best);
            float p = 1.0f / s;
            g_route[t] = be;
            g_prob[t] = p;
            int slot = atomicAdd(&g_cnt[be], 1);
            g_slot[t] = slot;
            if (slot < CAP) g_tok[be * CAP + slot] = t;
        }
    }
}

__global__ void __launch_bounds__(256) prep_kernel(const float* __restrict__ x,
                                                   const float* __restrict__ sw,
                                                   const float* __restrict__ sb,
                                                   const float* __restrict__ w1,
                                                   const float* __restrict__ w2) {
    __shared__ float tile[64][33];
    int b = blockIdx.x;
    if (b < PREP_W1) {
        int per_e = (DDIM / 64) * (FDIM / 32);
        int e = b / per_e, rem = b % per_e;
        int cx = rem % (FDIM / 32), ry = rem / (FDIM / 32);
        transpose_block64(w1, g_w1t, DDIM, FDIM, e, cx, ry, tile);
    } else if (b < PREP_W1 + PREP_W2) {
        int bb = b - PREP_W1;
        int per_e = (FDIM / 64) * (DDIM / 32);
        int e = bb / per_e, rem = bb % per_e;
        int cx = rem % (DDIM / 32), ry = rem / (DDIM / 32);
        transpose_block64(w2, g_w2t, FDIM, DDIM, e, cx, ry, tile);
    } else {
        router_block(x, sw, sb, b - PREP_W1 - PREP_W2);
    }
}

// gather + passthrough fused
__global__ void gather_kernel(const float* __restrict__ x, float* __restrict__ out) {
    int t = blockIdx.x;
    int e = g_route[t];
    int s = g_slot[t];
    const float4* src = (const float4*)(x + (size_t)t * DDIM);
    if (s < CAP) {
        __half2* dst = (__half2*)(g_Xbuf + ((size_t)e * CAP + s) * DDIM);
        for (int i = threadIdx.x; i < DDIM / 4; i += blockDim.x) {
            float4 v = src[i];
            dst[i * 2]     = __floats2half2_rn(v.x, v.y);
            dst[i * 2 + 1] = __floats2half2_rn(v.z, v.w);
        }
    } else {
        float p = g_prob[t];
        float4* dst = (float4*)(out + (size_t)t * DDIM);
        for (int i = threadIdx.x; i < DDIM / 4; i += blockDim.x) {
            float4 v = src[i];
            v.x *= p; v.y *= p; v.z *= p; v.w *= p;
            dst[i] = v;
        }
    }
}

// ===================== GEMM core (measured-best R10 structure) ===============
// CTA tile 64(M) x 128(N), K-chunk 64, 128 threads = 4 warps in 2(M) x 2(N),
// warp tile 32x64. 2 stages: A @ 0/8K, B @ 16K/32K. 48KB -> 4 CTAs/SM.
constexpr int SMEM_A_STAGE = 8192;
constexpr int SMEM_B_BASE  = 16384;
constexpr int SMEM_B_STAGE = 16384;
constexpr int SMEM_BYTES   = 49152;

__device__ __forceinline__ void issue_chunk(const __half* Ak, const __half* Bk,
                                            int ld, uint32_t sb, int buf, int tid) {
    uint32_t abase = sb + buf * SMEM_A_STAGE;
    uint32_t bbase = sb + SMEM_B_BASE + buf * SMEM_B_STAGE;
#pragma unroll
    for (int it = 0; it < 4; ++it) {
        int u = it * 128 + tid;
        int row = u >> 3, seg = u & 7;
        CP_ASYNC16(abase + SMEM_SWIZZLE_128B(row * 128 + seg * 16),
                   (const char*)(Ak + (size_t)row * ld) + seg * 16);
    }
#pragma unroll
    for (int it = 0; it < 8; ++it) {
        int u = it * 128 + tid;
        int row = u >> 3, seg = u & 7;
        CP_ASYNC16(bbase + SMEM_SWIZZLE_128B(row * 128 + seg * 16),
                   (const char*)(Bk + (size_t)row * ld) + seg * 16);
    }
}

__device__ __forceinline__ void compute_chunk(uint32_t abase, uint32_t bbase,
                                              int wm, int wn, int lane,
                                              float acc[2][8][4]) {
#pragma unroll
    for (int ks = 0; ks < 4; ++ks) {
        uint32_t af[2][4];
#pragma unroll
        for (int mt = 0; mt < 2; ++mt) {
            int row = wm * 32 + mt * 16 + (lane & 15);
            int colb = ks * 32 + (lane >> 4) * 16;
            ldsm_x4(af[mt][0], af[mt][1], af[mt][2], af[mt][3],
                    abase + SMEM_SWIZZLE_128B(row * 128 + colb));
        }
        uint32_t bf[8][2];
#pragma unroll
        for (int np = 0; np < 4; ++np) {
            int nrow = wn * 64 + np * 16 + (lane >> 4) * 8 + (lane & 7);
            int colb = ks * 32 + ((lane >> 3) & 1) * 16;
            uint32_t r0, r1, r2, r3;
            ldsm_x4(r0, r1, r2, r3, bbase + SMEM_SWIZZLE_128B(nrow * 128 + colb));
            bf[np * 2][0] = r0;     bf[np * 2][1] = r1;
            bf[np * 2 + 1][0] = r2; bf[np * 2 + 1][1] = r3;
        }
#pragma unroll
        for (int mt = 0; mt < 2; ++mt)
#pragma unroll
            for (int nt = 0; nt < 8; ++nt)
                mma16816(acc[mt][nt], af[mt], bf[nt]);
    }
}

__device__ __forceinline__ void gemm_mainloop(int nk, const __half* Ab, const __half* Bb,
                                              int ld, uint32_t sb, int tid,
                                              int wm, int wn, int lane,
                                              float acc[2][8][4]) {
    issue_chunk(Ab, Bb, ld, sb, 0, tid);
    CP_COMMIT();
    for (int kc = 0; kc < nk; ++kc) {
        if (kc + 1 < nk) {
            issue_chunk(Ab + (kc + 1) * 64, Bb + (kc + 1) * 64, ld, sb, (kc + 1) & 1, tid);
            CP_COMMIT();
            CP_WAIT(1);
        } else {
            CP_WAIT(0);
        }
        __syncthreads();
        compute_chunk(sb + (kc & 1) * SMEM_A_STAGE,
                      sb + SMEM_B_BASE + (kc & 1) * SMEM_B_STAGE,
                      wm, wn, lane, acc);
        __syncthreads();
    }
}

__device__ __forceinline__ float gelu_exact(float v) {
    return 0.5f * v * (1.0f + erff(v * 0.70710678118654752f));
}

// ===================== fused GEMM kernel ======================================
// 1D grid: [0, NB1) = gemm1 producer blocks, [NB1, NB1+NB2) = gemm2 consumers.
// Producers count completed f-blocks per (e, m-tile); consumers acquire-spin.
// Dispatch is in increasing block-index order, so every producer is dispatched
// before any consumer starts -> spin-wait is deadlock-free.
constexpr int NB1 = (FDIM / 128) * MB * NEXP;   // 7680
constexpr int NB2 = (DDIM / 128) * MB * NEXP;   // 1920

__global__ void __launch_bounds__(128, 4) moe_gemm_kernel(
    const float* __restrict__ b1, const float* __restrict__ b2,
    float* __restrict__ out)
{
    extern __shared__ char smem[];
    uint32_t sb = smem_u32(smem);
    int tid = threadIdx.x, lane = tid & 31, w = tid >> 5;
    int wm = w & 1, wn = w >> 1;
    int b = blockIdx.x;

    if (b < NB1) {
        // ---------------- GEMM1: H = gelu(Xbuf @ w1t^T + b1) ----------------
        int f = b % (FDIM / 128);
        int rest = b / (FDIM / 128);
        int mb = rest % MB;
        int e  = rest / MB;
        int m0 = mb * 64, f0 = f * 128;
        int cnt = g_cnt[e];
        int mcnt = cnt < CAP ? cnt : CAP;
        if (m0 >= mcnt) return;

        float acc[2][8][4];
#pragma unroll
        for (int a = 0; a < 2; a++)
#pragma unroll
            for (int bb_ = 0; bb_ < 8; bb_++)
#pragma unroll
                for (int c = 0; c < 4; c++) acc[a][bb_][c] = 0.f;

        const __half* Ab = g_Xbuf + ((size_t)e * CAP + m0) * DDIM;
        const __half* Bb = g_w1t + (size_t)e * FDIM * DDIM + (size_t)f0 * DDIM;
        gemm_mainloop(DDIM / 64, Ab, Bb, DDIM, sb, tid, wm, wn, lane, acc);

        const float* bb = b1 + (size_t)e * FDIM + f0 + wn * 64;
        __half* Hb = g_H + ((size_t)e * CAP + m0) * FDIM + f0;
        int lq = lane >> 2, lr = lane & 3;
#pragma unroll
        for (int nt = 0; nt < 8; ++nt) {
            float bc0 = bb[nt * 8 + lr * 2];
            float bc1 = bb[nt * 8 + lr * 2 + 1];
            int col = wn * 64 + nt * 8 + lr * 2;
#pragma unroll
            for (int mt = 0; mt < 2; ++mt) {
                int r0 = wm * 32 + mt * 16 + lq;
                __half2 v0 = __floats2half2_rn(gelu_exact(acc[mt][nt][0] + bc0),
                                               gelu_exact(acc[mt][nt][1] + bc1));
                __half2 v1 = __floats2half2_rn(gelu_exact(acc[mt][nt][2] + bc0),
                                               gelu_exact(acc[mt][nt][3] + bc1));
                *(__half2*)(Hb + (size_t)r0 * FDIM + col) = v0;
                *(__half2*)(Hb + (size_t)(r0 + 8) * FDIM + col) = v1;
            }
        }
        // publish: all H stores visible, then bump the tile counter
        __threadfence();
        __syncthreads();
        if (tid == 0) atomicAdd(&g_dep[e * MB + mb], 1);
    } else {
        // ---------------- GEMM2: out = (H @ w2t^T + b2) * prob --------------
        int b2i = b - NB1;
        int n = b2i % (DDIM / 128);
        int rest = b2i / (DDIM / 128);
        int mb = rest % MB;
        int e  = rest / MB;
        int m0 = mb * 64, n0 = n * 128;
        int cnt = g_cnt[e];
        int mcnt = cnt < CAP ? cnt : CAP;
        if (m0 >= mcnt) return;

        // wait for all 24 producer f-blocks of this (e, m-tile)
        if (tid == 0) {
            const int* dep = g_dep + e * MB + mb;
            int v;
            do {
                asm volatile("ld.global.acquire.gpu.b32 %0, [%1];"
                             : "=r"(v) : "l"(dep) : "memory");
                if (v < (FDIM / 128)) __nanosleep(128);
            } while (v < (FDIM / 128));
        }
        __syncthreads();

        float acc[2][8][4];
#pragma unroll
        for (int a = 0; a < 2; a++)
#pragma unroll
            for (int bb_ = 0; bb_ < 8; bb_++)
#pragma unroll
                for (int c = 0; c < 4; c++) acc[a][bb_][c] = 0.f;

        const __half* Ab = g_H + ((size_t)e * CAP + m0) * FDIM;
        const __half* Bb = g_w2t + (size_t)e * DDIM * FDIM + (size_t)n0 * FDIM;
        gemm_mainloop(FDIM / 64, Ab, Bb, FDIM, sb, tid, wm, wn, lane, acc);

        const float* bb = b2 + (size_t)e * DDIM + n0 + wn * 64;
        int lq = lane >> 2, lr = lane & 3;
        float bc0[8], bc1[8];
#pragma unroll
        for (int nt = 0; nt < 8; ++nt) {
            bc0[nt] = bb[nt * 8 + lr * 2];
            bc1[nt] = bb[nt * 8 + lr * 2 + 1];
        }
#pragma unroll
        for (int mt = 0; mt < 2; ++mt) {
#pragma unroll
            for (int half = 0; half < 2; ++half) {
                int row = wm * 32 + mt * 16 + lq + half * 8;
                int gm = m0 + row;
                if (gm < mcnt) {
                    int tok = g_tok[e * CAP + gm];
                    float p = g_prob[tok];
                    float* orow = out + (size_t)tok * DDIM + n0 + wn * 64;
#pragma unroll
                    for (int nt = 0; nt < 8; ++nt) {
                        float2 v;
                        v.x = (acc[mt][nt][half * 2]     + bc0[nt]) * p;
                        v.y = (acc[mt][nt][half * 2 + 1] + bc1[nt]) * p;
                        *(float2*)(orow + nt * 8 + lr * 2) = v;
                    }
                }
            }
        }
    }
}

// ===================== launch =====================
extern "C" void kernel_launch(void* const* d_in, const int* in_sizes, int n_in,
                              void* d_out, int out_size) {
    const float* x   = (const float*)d_in[0];
    const float* sw  = (const float*)d_in[1];
    const float* sbv = (const float*)d_in[2];
    const float* w1  = (const float*)d_in[3];
    const float* b1  = (const float*)d_in[4];
    const float* w2  = (const float*)d_in[5];
    const float* b2  = (const float*)d_in[6];
    float* out = (float*)d_out;

    cudaFuncSetAttribute(moe_gemm_kernel, cudaFuncAttributeMaxDynamicSharedMemorySize, SMEM_BYTES);

    zero_cnt_kernel<<<1, 256>>>();
    prep_kernel<<<PREP_BLOCKS, 256>>>(x, sw, sbv, w1, w2);
    gather_kernel<<<NTOK, 192>>>(x, out);
    moe_gemm_kernel<<<NB1 + NB2, 128, SMEM_BYTES>>>(b1, b2, out);
}